// round 2
// baseline (speedup 1.0000x reference)
#include <cuda_runtime.h>
#include <cstdint>

// Problem: out[tok, :] = sum_{l=0..7} weight[l, x[tok, l], :]
//   x:      (8, 2048, 8) indices (JAX int64 -> int32 on device, x64 disabled)
//   weight: (8, 1024, 1024) float32 -> 32 MB, L2-resident
//   out:    (8, 2048, 1024) float32

static constexpr int NTOK = 8 * 2048;   // 16384
static constexpr int L    = 8;
static constexpr int K    = 1024;
static constexpr int D    = 1024;
static constexpr int D4   = D / 4;      // 256 float4 per row

__global__ __launch_bounds__(256, 6)
void multi_embed_kernel(const int* __restrict__ x,
                        const float4* __restrict__ w,
                        float4* __restrict__ out)
{
    const int tok = blockIdx.x;
    const int tid = threadIdx.x;

    // Stage the 8 indices for this token in shared (broadcast once).
    __shared__ int s_idx[L];
    if (tid < L) {
        s_idx[tid] = x[tok * L + tid];
    }
    __syncthreads();

    // Front-batch 8 independent 16B loads (MLP=8) to hide L2 latency.
    float4 v[L];
#pragma unroll
    for (int l = 0; l < L; ++l) {
        const float4* row = w + ((size_t)(l * K + s_idx[l])) * D4;
        v[l] = __ldg(row + tid);
    }

    float4 acc;
    acc.x = v[0].x; acc.y = v[0].y; acc.z = v[0].z; acc.w = v[0].w;
#pragma unroll
    for (int l = 1; l < L; ++l) {
        acc.x += v[l].x;
        acc.y += v[l].y;
        acc.z += v[l].z;
        acc.w += v[l].w;
    }

    out[(size_t)tok * D4 + tid] = acc;
}

extern "C" void kernel_launch(void* const* d_in, const int* in_sizes, int n_in,
                              void* d_out, int out_size)
{
    const int*    x = (const int*)d_in[0];     // int32 indices
    const float4* w = (const float4*)d_in[1];  // weight, float32
    float4*       o = (float4*)d_out;

    multi_embed_kernel<<<NTOK, 256>>>(x, w, o);
}

// round 3
// speedup vs baseline: 1.4904x; 1.4904x over previous
#include <cuda_runtime.h>
#include <cstdint>

// out[tok, :] = sum_{l=0..7} weight[l, x[tok, l], :]
//   x:      16384 tokens x 8 int32 indices
//   weight: (8, 1024, 1024) f32, 32 MB (L2-resident)
//   out:    16384 x 1024 f32

static constexpr int NTOK = 8 * 2048;   // 16384
static constexpr int L    = 8;
static constexpr int K    = 1024;
static constexpr int D4   = 1024 / 4;   // 256 float4 per row

__global__ __launch_bounds__(256, 8)
void multi_embed_kernel(const int* __restrict__ x,
                        const float4* __restrict__ w,
                        float4* __restrict__ out)
{
    const int tok  = blockIdx.x;
    const int tid  = threadIdx.x;
    const int lane = tid & 31;

    // Broadcast the 8 indices within each warp via shfl (no barrier, no smem).
    int my = 0;
    if (lane < L) my = __ldg(x + tok * L + lane);

    // Batch 1: 4 independent LDG.128 in flight.
    float4 a0, a1, a2, a3;
    {
        int i0 = __shfl_sync(0xffffffffu, my, 0);
        int i1 = __shfl_sync(0xffffffffu, my, 1);
        int i2 = __shfl_sync(0xffffffffu, my, 2);
        int i3 = __shfl_sync(0xffffffffu, my, 3);
        a0 = __ldg(w + ((size_t)(0 * K + i0)) * D4 + tid);
        a1 = __ldg(w + ((size_t)(1 * K + i1)) * D4 + tid);
        a2 = __ldg(w + ((size_t)(2 * K + i2)) * D4 + tid);
        a3 = __ldg(w + ((size_t)(3 * K + i3)) * D4 + tid);
    }

    // Batch 2 addresses + loads issued while batch 1 is reduced.
    float4 b0, b1, b2, b3;
    {
        int i4 = __shfl_sync(0xffffffffu, my, 4);
        int i5 = __shfl_sync(0xffffffffu, my, 5);
        int i6 = __shfl_sync(0xffffffffu, my, 6);
        int i7 = __shfl_sync(0xffffffffu, my, 7);
        b0 = __ldg(w + ((size_t)(4 * K + i4)) * D4 + tid);
        b1 = __ldg(w + ((size_t)(5 * K + i5)) * D4 + tid);
        b2 = __ldg(w + ((size_t)(6 * K + i6)) * D4 + tid);
        b3 = __ldg(w + ((size_t)(7 * K + i7)) * D4 + tid);
    }

    float4 acc;
    acc.x = (a0.x + a1.x) + (a2.x + a3.x);
    acc.y = (a0.y + a1.y) + (a2.y + a3.y);
    acc.z = (a0.z + a1.z) + (a2.z + a3.z);
    acc.w = (a0.w + a1.w) + (a2.w + a3.w);

    acc.x += (b0.x + b1.x) + (b2.x + b3.x);
    acc.y += (b0.y + b1.y) + (b2.y + b3.y);
    acc.z += (b0.z + b1.z) + (b2.z + b3.z);
    acc.w += (b0.w + b1.w) + (b2.w + b3.w);

    // Streaming store: evict-first in L2 so output writes don't evict the
    // L2-resident weight table.
    float4* dst = out + (size_t)tok * D4 + tid;
    asm volatile("st.global.cs.v4.f32 [%0], {%1, %2, %3, %4};"
                 :: "l"(dst), "f"(acc.x), "f"(acc.y), "f"(acc.z), "f"(acc.w)
                 : "memory");
}

extern "C" void kernel_launch(void* const* d_in, const int* in_sizes, int n_in,
                              void* d_out, int out_size)
{
    const int*    x = (const int*)d_in[0];
    const float4* w = (const float4*)d_in[1];
    float4*       o = (float4*)d_out;

    multi_embed_kernel<<<NTOK, 256>>>(x, w, o);
}

// round 4
// speedup vs baseline: 1.5668x; 1.0513x over previous
#include <cuda_runtime.h>
#include <cstdint>

// out[tok, :] = sum_{l=0..7} weight[l, x[tok, l], :]
//   x:      16384 tokens x 8 int32 indices
//   weight: (8, 1024, 1024) f32, 32 MB (mostly L2-resident, partly L1-reused)
//   out:    16384 x 1024 f32

static constexpr int NTOK = 8 * 2048;   // 16384
static constexpr int K    = 1024;
static constexpr int D4   = 1024 / 4;   // 256 float4 per row

__global__ __launch_bounds__(256, 8)
void multi_embed_kernel(const int4* __restrict__ x4,
                        const float4* __restrict__ w,
                        float4* __restrict__ out)
{
    const int tok = blockIdx.x;
    const int tid = threadIdx.x;

    // All 8 indices via two uniform 16B loads (warp-broadcast, no shfl/smem).
    const int4 iA = __ldg(x4 + tok * 2);       // l = 0..3
    const int4 iB = __ldg(x4 + tok * 2 + 1);   // l = 4..7

    const float4* wt = w + tid;

    // Batch 1: 4 independent LDG.128 in flight.
    float4 a0 = __ldg(wt + (size_t)(0 * K + iA.x) * D4);
    float4 a1 = __ldg(wt + (size_t)(1 * K + iA.y) * D4);
    float4 a2 = __ldg(wt + (size_t)(2 * K + iA.z) * D4);
    float4 a3 = __ldg(wt + (size_t)(3 * K + iA.w) * D4);

    // Batch 2 issued while batch 1 is reduced.
    float4 b0 = __ldg(wt + (size_t)(4 * K + iB.x) * D4);
    float4 b1 = __ldg(wt + (size_t)(5 * K + iB.y) * D4);
    float4 b2 = __ldg(wt + (size_t)(6 * K + iB.z) * D4);
    float4 b3 = __ldg(wt + (size_t)(7 * K + iB.w) * D4);

    float4 acc;
    acc.x = (a0.x + a1.x) + (a2.x + a3.x);
    acc.y = (a0.y + a1.y) + (a2.y + a3.y);
    acc.z = (a0.z + a1.z) + (a2.z + a3.z);
    acc.w = (a0.w + a1.w) + (a2.w + a3.w);

    acc.x += (b0.x + b1.x) + (b2.x + b3.x);
    acc.y += (b0.y + b1.y) + (b2.y + b3.y);
    acc.z += (b0.z + b1.z) + (b2.z + b3.z);
    acc.w += (b0.w + b1.w) + (b2.w + b3.w);

    // Streaming store: evict-first so output writes don't evict weight lines.
    float4* dst = out + (size_t)tok * D4 + tid;
    asm volatile("st.global.cs.v4.f32 [%0], {%1, %2, %3, %4};"
                 :: "l"(dst), "f"(acc.x), "f"(acc.y), "f"(acc.z), "f"(acc.w)
                 : "memory");
}

extern "C" void kernel_launch(void* const* d_in, const int* in_sizes, int n_in,
                              void* d_out, int out_size)
{
    const int4*   x = (const int4*)d_in[0];
    const float4* w = (const float4*)d_in[1];
    float4*       o = (float4*)d_out;

    multi_embed_kernel<<<NTOK, 256>>>(x, w, o);
}